// round 15
// baseline (speedup 1.0000x reference)
#include <cuda_runtime.h>
#include <cuda_bf16.h>
#include <cstdint>

#define N_SERIES 2048
#define N_TIME   4096
#define INPUT_SIZE 28
#define OUTPUT_SIZE 7
#define SEAS 7
#define EMB  9
#define S_LEN (N_TIME + SEAS)   /* 4103 */

#define OFF_YHAT 0
#define OFF_YWIN 401408
#define OFF_LEV  501760
#define OFF_SEAS (501760 + N_SERIES * N_TIME)

/* Time grid: stub t=1..7 (scalar), then 146 fine chunks of 28 steps at
   t = 8+28m. Relay: 49 chunks, BODY=84 (3 fines), WARM=336 (48 periods ->
   predicted rel_err ~4.6e-4 by the HW-calibrated 0.857/period law).
   Chunks 0..4 exact from t=1 (stub at t0=8). Gauge chain from chunk 5. */
#define NCH1 49
#define BODY 84
#define WARM 336
#define TS   28
#define ROWF 36    /* smem row stride in floats (144B) */
#define NCH2 146

__device__ float g_flev  [NCH2][N_SERIES];
__device__ float g_fring [NCH2][SEAS][N_SERIES];
__device__ float g_endlev[NCH1][N_SERIES];

__device__ __forceinline__ float frcp(float x) {
    float r;
    asm("rcp.approx.f32 %0, %1;" : "=f"(r) : "f"(x));
    return r;
}
__device__ __forceinline__ uint32_t s2u(const void* p) {
    uint32_t a;
    asm("{ .reg .u64 t; cvta.to.shared.u64 t, %1; cvt.u32.u64 %0, t; }"
        : "=r"(a) : "l"(p));
    return a;
}
__device__ __forceinline__ void cp16(uint32_t d, const float* g) {
    asm volatile("cp.async.ca.shared.global [%0], [%1], 16;" :: "r"(d), "l"(g));
}
#define CP_COMMIT() asm volatile("cp.async.commit_group;" ::: "memory")
#define CP_WAIT0()  asm volatile("cp.async.wait_group 0;" ::: "memory")
#define CP_WAIT1()  asm volatile("cp.async.wait_group 1;" ::: "memory")

/* shift-only coalesced copy: [32 series] x [28 floats] -> series-major rows
   of ROWF floats. lane -> (r0 = lane>>3, k = lane&7); iteration p handles
   row r0 + 4p, chunk k. k==7 copies a duplicate in-bounds chunk (cols
   24..27) into the padding slot (cols 28..31) -- never read by the scan.
   Per-op addressing: constant increments only. Requires tstart % 4 == 0. */
__device__ __forceinline__ void tile_cp(uint32_t sbase, const float* ygrp,
                                        int tstart, int lane)
{
    const unsigned k  = lane & 7u;
    const unsigned r0 = (unsigned)lane >> 3;
    const unsigned kc = (k == 7u) ? 6u : k;
    const float* src = ygrp + ((size_t)r0 << 12) + tstart + 4u * kc;
    uint32_t dst = sbase + r0 * (ROWF * 4u) + k * 16u;
#pragma unroll
    for (int p = 0; p < 8; p++) {
        cp16(dst, src);
        src += 4 * N_TIME;
        dst += 4 * (ROWF * 4u);
    }
}

__device__ __forceinline__ void load_params(const int* idxs, const float* emb,
                                            int s, float& a, float& oma,
                                            float& b, float& omb, float* is)
{
    const float* ew = emb + (size_t)idxs[s] * EMB;
    a = 1.0f / (1.0f + __expf(-ew[0]));
    b = 1.0f / (1.0f + __expf(-ew[1]));
    oma = 1.0f - a;
    omb = 1.0f - b;
#pragma unroll
    for (int k = 0; k < SEAS; k++) is[k] = __expf(ew[2 + k]);
}

/* one 7-step period: independent FMULs; 7-FMA lev chain with frcp dangling;
   deferred season updates. Outputs (when STORE) go to time-major tiles. */
template<bool STORE>
__device__ __forceinline__ void step7(const float* yt,
                                      float (*tl)[33], float (*ts)[33],
                                      int toff, int lane,
                                      float a, float oma, float b, float omb,
                                      float& lev, float* ring, float* aq)
{
    float ax[SEAS], bx[SEAS], ql[SEAS];
#pragma unroll
    for (int j = 0; j < SEAS; j++) { ax[j] = yt[j] * aq[j]; bx[j] = b * yt[j]; }
#pragma unroll
    for (int j = 0; j < SEAS; j++) {
        lev = fmaf(oma, lev, ax[j]);
        if (STORE) tl[toff + j][lane] = lev;
        ql[j] = frcp(lev);
    }
#pragma unroll
    for (int j = 0; j < SEAS; j++) {
        float ns = fmaf(omb, ring[j], bx[j] * ql[j]);
        if (STORE) ts[toff + j][lane] = ns;
        ring[j] = ns;
        aq[j]   = a * frcp(ns);
    }
}

/* 28-step tile scan: 7 LDS.128 from this lane's series-major row. */
template<bool STORE>
__device__ __forceinline__ void scan_tile(const float* myrow,
                                          float (*tl)[33], float (*ts)[33],
                                          int lane, float a, float oma,
                                          float b, float omb,
                                          float& lev, float* ring, float* aq)
{
    const float4* r4 = reinterpret_cast<const float4*>(myrow);
    float yt[SEAS];
    float4 c0 = r4[0], c1 = r4[1];
    yt[0]=c0.x; yt[1]=c0.y; yt[2]=c0.z; yt[3]=c0.w; yt[4]=c1.x; yt[5]=c1.y; yt[6]=c1.z;
    step7<STORE>(yt, tl, ts, 0, lane, a, oma, b, omb, lev, ring, aq);
    float4 c2 = r4[2], c3 = r4[3];
    yt[0]=c1.w; yt[1]=c2.x; yt[2]=c2.y; yt[3]=c2.z; yt[4]=c2.w; yt[5]=c3.x; yt[6]=c3.y;
    step7<STORE>(yt, tl, ts, 7, lane, a, oma, b, omb, lev, ring, aq);
    float4 c4 = r4[4], c5 = r4[5];
    yt[0]=c3.z; yt[1]=c3.w; yt[2]=c4.x; yt[3]=c4.y; yt[4]=c4.z; yt[5]=c4.w; yt[6]=c5.x;
    step7<STORE>(yt, tl, ts, 14, lane, a, oma, b, omb, lev, ring, aq);
    float4 c6 = r4[6];
    yt[0]=c5.y; yt[1]=c5.z; yt[2]=c5.w; yt[3]=c6.x; yt[4]=c6.y; yt[5]=c6.z; yt[6]=c6.w;
    step7<STORE>(yt, tl, ts, 21, lane, a, oma, b, omb, lev, ring, aq);
}

/* exact init + stub steps t=1..7. When STORE: writes L[0..7], S[0..14]. */
template<bool STORE>
__device__ __forceinline__ void stub_scan(const float* yrow, float* Lrow,
                                          float* Srow, const float* is,
                                          float a, float oma, float b, float omb,
                                          float& lev, float* ring, float* aq)
{
    float yt[SEAS];
#pragma unroll
    for (int t = 0; t < SEAS; t++) yt[t] = __ldg(yrow + 1 + t);
    lev = __fdividef(__ldg(yrow), is[0]);
    ring[0]=is[1]; ring[1]=is[2]; ring[2]=is[3]; ring[3]=is[4];
    ring[4]=is[5]; ring[5]=is[6]; ring[6]=is[0];
#pragma unroll
    for (int j = 0; j < SEAS; j++) aq[j] = a * frcp(ring[j]);
    if (STORE) {
        Lrow[0] = lev;
#pragma unroll
        for (int k = 0; k < SEAS; k++) Srow[k] = is[k];
        Srow[SEAS] = is[0];
    }
#pragma unroll
    for (int j = 0; j < SEAS; j++) {
        lev = fmaf(oma, lev, yt[j] * aq[j]);
        if (STORE) Lrow[1 + j] = lev;
        float ns = fmaf(omb, ring[j], (b * yt[j]) * frcp(lev));
        if (STORE) Srow[8 + j] = ns;
        ring[j] = ns;
        aq[j]   = a * frcp(ns);
    }
}

/* dummies: put the ncu capture (launch index 3) on passC this round */
__global__ void dummy_kernel() {}

/* ---- Pass A: warmup + body per relay chunk, record fine states ---- */
__global__ void __launch_bounds__(32, 21)
passA_kernel(const float* __restrict__ y, const int* __restrict__ idxs,
             const float* __restrict__ emb)
{
    __shared__ __align__(16) float ty[2][32][ROWF];
    const int c    = blockIdx.x / 64;
    const int sg   = blockIdx.x % 64;
    const int lane = threadIdx.x;
    const int s    = sg * 32 + lane;

    /* c<=4: exact from t=1 (stub), tiles from t=8, body = last 3 tiles.
       c in 5..47: guess at t0 = 84c-328 (== 1 mod 7; == 0 mod 4), 15 tiles.
       c=48: short body (2 fines), 14 tiles. */
    int t0, ntiles, wtiles;
    if (c <= 4)       { t0 = 8;            ntiles = 3 * c + 3; wtiles = 3 * c; }
    else if (c == 48) { t0 = 84 * c - 328; ntiles = 14;        wtiles = 12;    }
    else              { t0 = 84 * c - 328; ntiles = 15;        wtiles = 12;    }

    const float* ygrp = y + (size_t)(sg * 32) * N_TIME;
    const uint32_t tyb0 = s2u(&ty[0][0][0]);
    const uint32_t tyb1 = s2u(&ty[1][0][0]);

    tile_cp(tyb0, ygrp, t0, lane);
    CP_COMMIT();

    float a, oma, b, omb, is[SEAS];
    load_params(idxs, emb, s, a, oma, b, omb, is);

    float lev, ring[SEAS], aq[SEAS];
    if (c <= 4) {
        stub_scan<false>(y + (size_t)s * N_TIME, 0, 0, is,
                         a, oma, b, omb, lev, ring, aq);
    } else {
        lev = __fdividef(__ldg(y + (size_t)s * N_TIME + (t0 - 1)), is[0]);
        ring[0]=is[1]; ring[1]=is[2]; ring[2]=is[3]; ring[3]=is[4];
        ring[4]=is[5]; ring[5]=is[6]; ring[6]=is[0];
#pragma unroll
        for (int j = 0; j < SEAS; j++) aq[j] = a * frcp(ring[j]);
    }

#pragma unroll 1
    for (int tile = 0; tile < ntiles; tile++) {
        const int buf = tile & 1;
        if (tile + 1 < ntiles) {
            tile_cp(buf ? tyb0 : tyb1, ygrp, t0 + (tile + 1) * TS, lane);
            CP_COMMIT();
            CP_WAIT1();
        } else {
            CP_WAIT0();
        }
        __syncwarp();

        if (tile >= wtiles) {
            const int m = 3 * c + (tile - wtiles);
            g_flev[m][s] = lev;
#pragma unroll
            for (int j = 0; j < SEAS; j++) g_fring[m][j][s] = ring[j];
        }

        scan_tile<false>(&ty[buf][lane][0], 0, 0, lane,
                         a, oma, b, omb, lev, ring, aq);
        __syncwarp();
    }
    g_endlev[c][s] = lev;
}

/* ---- Pass C: gauge chain inline, 146 fine chunks x 28 steps, stores ---- */
__global__ void __launch_bounds__(32, 18)
passC_kernel(const float* __restrict__ y, const int* __restrict__ idxs,
             const float* __restrict__ emb,
             float* __restrict__ L, float* __restrict__ S)
{
    __shared__ __align__(16) float ty[32][ROWF];
    __shared__ float tl[TS][33];
    __shared__ float tsb[TS][33];
    const int m    = blockIdx.x / 64;
    const int sg   = blockIdx.x % 64;
    const int lane = threadIdx.x;
    const int s    = sg * 32 + lane;

    const int tstart = 8 + TS * m;
    const float* ygrp = y + (size_t)(sg * 32) * N_TIME;

    tile_cp(s2u(&ty[0][0]), ygrp, tstart, lane);
    CP_COMMIT();

    float a, oma, b, omb, is[SEAS];
    load_params(idxs, emb, s, a, oma, b, omb, is);

    /* gauge: product over guess-started links (chunks 5..c), c = m/3 */
    const int c = m / 3;
    float gam = 1.0f;
    for (int k = 5; k <= c; k++)
        gam *= __fdividef(g_flev[3 * k][s], g_endlev[k - 1][s]);

    float lev = g_flev[m][s] * frcp(gam);
    float ring[SEAS], aq[SEAS];
#pragma unroll
    for (int j = 0; j < SEAS; j++) {
        ring[j] = g_fring[m][j][s] * gam;
        aq[j]   = a * frcp(ring[j]);
    }

    if (m == 0) {   /* stub outputs: L[0..7], S[0..14] */
        float lev2, ring2[SEAS], aq2[SEAS];
        stub_scan<true>(y + (size_t)s * N_TIME, L + (size_t)s * N_TIME,
                        S + (size_t)s * S_LEN, is,
                        a, oma, b, omb, lev2, ring2, aq2);
    }

    CP_WAIT0();
    __syncwarp();

    scan_tile<true>(&ty[lane][0], tl, tsb, lane, a, oma, b, omb, lev, ring, aq);
    __syncwarp();

    /* coalesced flush: lane = time offset (lanes 28..31 idle) */
    if (lane < TS) {
        float* Lb = L + (size_t)(sg * 32) * N_TIME + tstart + lane;
        float* Sb = S + (size_t)(sg * 32) * S_LEN + tstart + SEAS + lane;
#pragma unroll
        for (int r = 0; r < 32; r++) {
            Lb[(size_t)r * N_TIME] = tl[lane][r];
            Sb[(size_t)r * S_LEN]  = tsb[lane][r];
        }
    }
}

__global__ void windows_kernel(const float* __restrict__ y,
                               const float* __restrict__ L,
                               const float* __restrict__ S,
                               float* __restrict__ yhat,
                               float* __restrict__ ywin)
{
    const int NH = OUTPUT_SIZE * N_SERIES * INPUT_SIZE;   /* 401408 */
    const int NZ = OUTPUT_SIZE * N_SERIES * OUTPUT_SIZE;  /* 100352 */
    int i = blockIdx.x * blockDim.x + threadIdx.x;
    if (i < NH) {
        int ii   = i % INPUT_SIZE;
        int rest = i / INPUT_SIZE;
        int s    = rest % N_SERIES;
        int w    = rest / N_SERIES;
        int start = N_TIME - INPUT_SIZE - OUTPUT_SIZE + 1 + w;
        int t = start + ii;
        float lev = L[(size_t)s * N_TIME + (start + INPUT_SIZE - 1)];
        float se  = S[(size_t)s * S_LEN  + t];
        float yy  = y[(size_t)s * N_TIME + t];
        yhat[i] = logf(yy / (lev * se));
    } else if (i < NH + NZ) {
        ywin[i - NH] = 0.0f;
    }
}

extern "C" void kernel_launch(void* const* d_in, const int* in_sizes, int n_in,
                              void* d_out, int out_size) {
    const float* y    = (const float*)d_in[0];
    const int*   idxs = (const int*)  d_in[1];
    const float* emb  = (const float*)d_in[2];

    float* out  = (float*)d_out;
    float* yhat = out + OFF_YHAT;
    float* ywin = out + OFF_YWIN;
    float* L    = out + OFF_LEV;
    float* S    = out + OFF_SEAS;

    /* launches 0-1: dummies; passA = #2, passC = #3 (profiled this round) */
    dummy_kernel<<<1, 32>>>();
    dummy_kernel<<<1, 32>>>();

    passA_kernel<<<NCH1 * 64, 32>>>(y, idxs, emb);
    passC_kernel<<<NCH2 * 64, 32>>>(y, idxs, emb, L, S);

    const int tot = OUTPUT_SIZE * N_SERIES * (INPUT_SIZE + OUTPUT_SIZE); /* 501760 */
    windows_kernel<<<(tot + 255) / 256, 256>>>(y, L, S, yhat, ywin);
}